// round 10
// baseline (speedup 1.0000x reference)
#include <cuda_runtime.h>
#include <cuda_bf16.h>
#include <cstdint>
#include <math.h>

#define B_  32
#define N_  64
#define D_  30
#define ND_ 64
#define H3_ 32
#define L_  8

// ---------------- device scratch ----------------
__device__ float g_xenc[B_*N_*H3_];
__device__ float g_x2[B_*N_];
__device__ float g_denc[D_*ND_*H3_];
__device__ float g_dsamp[D_*ND_*H3_];
__device__ float g_y2[D_*ND_];
__device__ float g_klpart[D_];
__device__ float4 g_vwd[D_*N_*ND_];          // [d][i] -> (s, t0, t1, t2)  2 MB
__device__ float4 g_part[L_*B_*D_];          // per (l,b,d) partial (s,t0,t1,t2)

__constant__ float c_lamda[8] = {0.01f,0.1f,0.5f,1.0f,3.0f,5.0f,10.0f,20.0f};

// ---------------- JAX threefry2x32 (partitionable) ------------------
__device__ __forceinline__ uint32_t rotl32(uint32_t x, int r){
    return (x << r) | (x >> (32 - r));
}
__device__ float jax_uniform_1920(int i){
    uint32_t x0 = 0u;
    uint32_t x1 = (uint32_t)i;
    const uint32_t k0 = 0u, k1 = 42u;
    const uint32_t k2 = 0u ^ 42u ^ 0x1BD11BDAu;
    x0 += k0; x1 += k1;
    #define FOUR_ROUNDS(a,b,c,d) \
        x0 += x1; x1 = rotl32(x1,a); x1 ^= x0; \
        x0 += x1; x1 = rotl32(x1,b); x1 ^= x0; \
        x0 += x1; x1 = rotl32(x1,c); x1 ^= x0; \
        x0 += x1; x1 = rotl32(x1,d); x1 ^= x0;
    FOUR_ROUNDS(13,15,26,6);  x0 += k1; x1 += k2 + 1u;
    FOUR_ROUNDS(17,29,16,24); x0 += k2; x1 += k0 + 2u;
    FOUR_ROUNDS(13,15,26,6);  x0 += k0; x1 += k1 + 3u;
    FOUR_ROUNDS(17,29,16,24); x0 += k1; x1 += k2 + 4u;
    FOUR_ROUNDS(13,15,26,6);  x0 += k2; x1 += k0 + 5u;
    #undef FOUR_ROUNDS
    uint32_t bits = x0 ^ x1;
    uint32_t fb = (bits >> 9) | 0x3f800000u;
    return __uint_as_float(fb) - 1.0f;
}

// ---------------- GCN (both branches in one launch) ----------------------
__global__ void gcn_kernel(
    const float* __restrict__ xg0, const float* __restrict__ adjg0,
    const float* __restrict__ eW1, const float* __restrict__ eb1,
    const float* __restrict__ eW2, const float* __restrict__ eb2,
    const float* __restrict__ eW3, const float* __restrict__ eb3,
    const float* __restrict__ xg1, const float* __restrict__ adjg1,
    const float* __restrict__ dW1, const float* __restrict__ db1,
    const float* __restrict__ dW2, const float* __restrict__ db2,
    const float* __restrict__ dW3, const float* __restrict__ db3)
{
    extern __shared__ float sm[];
    float* adj_s = sm;             // 4096
    float* x_s   = sm + 4096;      // 4096
    float* t     = sm + 8192;      // 8192
    float* h     = sm + 16384;     // 8192
    int branch = (blockIdx.x >= 32) ? 1 : 0;
    int g = branch ? (blockIdx.x - 32) : blockIdx.x;
    const float* x   = (branch ? xg1   : xg0)   + g*64*64;
    const float* adj = (branch ? adjg1 : adjg0) + g*64*64;
    const float* W1 = branch ? dW1 : eW1; const float* b1 = branch ? db1 : eb1;
    const float* W2 = branch ? dW2 : eW2; const float* b2 = branch ? db2 : eb2;
    const float* W3 = branch ? dW3 : eW3; const float* b3 = branch ? db3 : eb3;
    int tid = threadIdx.x;

    for (int i = tid; i < 4096; i += 256){ adj_s[i] = adj[i]; x_s[i] = x[i]; }
    __syncthreads();

    for (int idx = tid; idx < 16*128; idx += 256){
        int rg = idx >> 7, j = idx & 127;
        const float* xr = x_s + rg*4*64;
        float a0=0.f,a1=0.f,a2=0.f,a3=0.f;
        #pragma unroll 8
        for (int k = 0; k < 64; k++){
            float w = W1[k*128+j];
            a0 += xr[k]*w; a1 += xr[64+k]*w; a2 += xr[128+k]*w; a3 += xr[192+k]*w;
        }
        t[(rg*4+0)*128+j]=a0; t[(rg*4+1)*128+j]=a1; t[(rg*4+2)*128+j]=a2; t[(rg*4+3)*128+j]=a3;
    }
    __syncthreads();
    for (int idx = tid; idx < 16*128; idx += 256){
        int rg = idx >> 7, j = idx & 127;
        const float* ar = adj_s + rg*4*64;
        float bb = b1[j];
        float a0=bb,a1=bb,a2=bb,a3=bb;
        #pragma unroll 8
        for (int k = 0; k < 64; k++){
            float w = t[k*128+j];
            a0 += ar[k]*w; a1 += ar[64+k]*w; a2 += ar[128+k]*w; a3 += ar[192+k]*w;
        }
        h[(rg*4+0)*128+j]=fmaxf(a0,0.f); h[(rg*4+1)*128+j]=fmaxf(a1,0.f);
        h[(rg*4+2)*128+j]=fmaxf(a2,0.f); h[(rg*4+3)*128+j]=fmaxf(a3,0.f);
    }
    __syncthreads();
    for (int idx = tid; idx < 16*64; idx += 256){
        int rg = idx >> 6, j = idx & 63;
        const float* hr = h + rg*4*128;
        float a0=0.f,a1=0.f,a2=0.f,a3=0.f;
        #pragma unroll 8
        for (int k = 0; k < 128; k++){
            float w = W2[k*64+j];
            a0 += hr[k]*w; a1 += hr[128+k]*w; a2 += hr[256+k]*w; a3 += hr[384+k]*w;
        }
        t[(rg*4+0)*64+j]=a0; t[(rg*4+1)*64+j]=a1; t[(rg*4+2)*64+j]=a2; t[(rg*4+3)*64+j]=a3;
    }
    __syncthreads();
    for (int idx = tid; idx < 16*64; idx += 256){
        int rg = idx >> 6, j = idx & 63;
        const float* ar = adj_s + rg*4*64;
        float bb = b2[j];
        float a0=bb,a1=bb,a2=bb,a3=bb;
        #pragma unroll 8
        for (int k = 0; k < 64; k++){
            float w = t[k*64+j];
            a0 += ar[k]*w; a1 += ar[64+k]*w; a2 += ar[128+k]*w; a3 += ar[192+k]*w;
        }
        h[(rg*4+0)*64+j]=fmaxf(a0,0.f); h[(rg*4+1)*64+j]=fmaxf(a1,0.f);
        h[(rg*4+2)*64+j]=fmaxf(a2,0.f); h[(rg*4+3)*64+j]=fmaxf(a3,0.f);
    }
    __syncthreads();
    for (int idx = tid; idx < 16*32; idx += 256){
        int rg = idx >> 5, j = idx & 31;
        const float* hr = h + rg*4*64;
        float a0=0.f,a1=0.f,a2=0.f,a3=0.f;
        #pragma unroll 8
        for (int k = 0; k < 64; k++){
            float w = W3[k*32+j];
            a0 += hr[k]*w; a1 += hr[64+k]*w; a2 += hr[128+k]*w; a3 += hr[192+k]*w;
        }
        t[(rg*4+0)*32+j]=a0; t[(rg*4+1)*32+j]=a1; t[(rg*4+2)*32+j]=a2; t[(rg*4+3)*32+j]=a3;
    }
    __syncthreads();
    float* outp = (branch == 0) ? (g_xenc + g*2048) : (g_denc + g*2048);
    for (int idx = tid; idx < 16*32; idx += 256){
        int rg = idx >> 5, j = idx & 31;
        const float* ar = adj_s + rg*4*64;
        float bb = b3[j];
        float a0=bb,a1=bb,a2=bb,a3=bb;
        #pragma unroll 8
        for (int k = 0; k < 64; k++){
            float w = t[k*32+j];
            a0 += ar[k]*w; a1 += ar[64+k]*w; a2 += ar[128+k]*w; a3 += ar[192+k]*w;
        }
        h[(rg*4+0)*32+j]=a0; h[(rg*4+1)*32+j]=a1; h[(rg*4+2)*32+j]=a2; h[(rg*4+3)*32+j]=a3;
        outp[(rg*4+0)*32+j]=a0; outp[(rg*4+1)*32+j]=a1; outp[(rg*4+2)*32+j]=a2; outp[(rg*4+3)*32+j]=a3;
    }
    __syncthreads();
    if (branch == 0 && tid < 64){
        float s = 0.f;
        #pragma unroll
        for (int f = 0; f < 32; f++){ float v = h[tid*32+f]; s += v*v; }
        g_x2[g*64 + tid] = s;
    }
}

// ---------------- prep: vwd precompute + attn/bernoulli (merged) ----------
__global__ void prep_kernel(const float* __restrict__ dp, const float* __restrict__ wl,
                            const float* __restrict__ fc1w, const float* __restrict__ fc2w,
                            const float* __restrict__ mlp_w, const float* __restrict__ mlp_b,
                            const float* __restrict__ mlp2_w, const float* __restrict__ mlp2_b)
{
    __shared__ float w3s[3*960];
    __shared__ float wls[960];
    __shared__ float yw[32][32];
    __shared__ float z[33];
    __shared__ float nrm[32];
    __shared__ float klsh[64];
    int tid = threadIdx.x;
    int d = blockIdx.x;

    // ---- vwd phase ----
    for (int e = tid; e < 960; e += 256) wls[e] = wl[e];
    for (int e = tid; e < 2880; e += 256){
        int c = e / 960, j = e - c*960;
        float acc = 0.f;
        #pragma unroll 8
        for (int r = 0; r < 64; r++) acc += fc2w[c*64+r] * fc1w[r*960+j];
        w3s[e] = acc;
    }
    // ---- attn phase part 1 (independent smem) ----
    for (int e = tid; e < 1024; e += 256){
        int b = e >> 5, f = e & 31;
        float ss = 0.f, sw = 0.f;
        #pragma unroll 8
        for (int n = 0; n < 64; n++){
            float v = g_xenc[(b*64+n)*32 + f];
            ss += v*v;
            sw += mlp_w[n]*v;
        }
        yw[b][f] = sw / (sqrtf(ss) + 1e-12f);
    }
    const float* de = g_denc + d*2048;
    if (tid >= 64 && tid < 96){
        int f = tid - 64;
        float s = 0.f;
        #pragma unroll 8
        for (int m = 0; m < 64; m++){ float v = de[m*32+f]; s += v*v; }
        nrm[f] = sqrtf(s) + 1e-12f;
    }
    __syncthreads();
    // vwd write-out
    {
        int base = d*32;
        for (int i = tid; i < 4096; i += 256){
            const float* dr = dp + (size_t)i*32;
            float s=0.f, t0=0.f, t1=0.f, t2=0.f;
            #pragma unroll 8
            for (int k = 0; k < 32; k++){
                float v = dr[k];
                s  += v * wls[base+k];
                t0 += v * w3s[base+k];
                t1 += v * w3s[960+base+k];
                t2 += v * w3s[1920+base+k];
            }
            g_vwd[d*4096 + i] = make_float4(s, t0, t1, t2);
        }
    }
    // z
    if (tid < 32){
        float acc = 0.f;
        #pragma unroll
        for (int b = 0; b < 32; b++) acc += mlp2_w[b]*yw[b][tid];
        z[tid] = acc;
    }
    if (tid == 32){
        float s = 0.f;
        #pragma unroll
        for (int b = 0; b < 32; b++) s += mlp2_w[b];
        z[32] = mlp_b[0]*s + mlp2_b[0];
    }
    __syncthreads();
    if (tid < 64){
        int m = tid;
        float p = z[32];
        #pragma unroll
        for (int f = 0; f < 32; f++) p += (de[m*32+f]/nrm[f]) * z[f];
        float attn = 1.f/(1.f + expf(-p));
        float u = jax_uniform_1920(d*64 + m);
        float bern = (u < attn) ? 1.f : 0.f;
        float ss = 0.f;
        #pragma unroll
        for (int f = 0; f < 32; f++){
            float v = de[m*32+f];
            g_dsamp[d*2048 + m*32+f] = bern*v;
            ss += v*v;
        }
        g_y2[d*64+m] = bern*ss;
        klsh[m] = attn*logf(attn*2.f) + (1.f-attn)*logf((1.f-attn)*2.f);
    }
    __syncthreads();
    if (tid == 0){
        float s = 0.f;
        for (int i = 0; i < 64; i++) s += klsh[i];
        g_klpart[d] = s;
    }
}

// ---------------- Sinkhorn: per (d,b), 8 lambdas; shuffle q-reduction -----
// thread map: c = tid>>2 (0..63), q = tid&3. Km in regs (regA col-slice,
// regB row-slice). ui/vi in permuted smem: addr(r) = (r&15)*4 + (r>>4).
// 2 syncthreads per sinkhorn iteration; row stats + final ui via shuffles.
__global__ void __launch_bounds__(256, 3)
sinkhorn_kernel(const int* __restrict__ num_node, const int* __restrict__ dict_nnode)
{
    __shared__ float Ms[64*65];
    __shared__ float xs[2048];
    __shared__ float ds[2048];
    __shared__ float ui_s[64];
    __shared__ float vi_s[64];
    __shared__ float4 wred[8];

    int d = blockIdx.x, b = blockIdx.y;
    int tid = threadIdx.x;
    int c = tid >> 2, q = tid & 3;
    int nn = num_node[b], dn = dict_nnode[d];
    float wis_c = (c < nn) ? 1.f/(float)nn : 0.f;
    float wjs_c = (c < dn) ? 1.f/(float)dn : 0.f;

    for (int i = tid; i < 2048; i += 256){
        xs[i] = g_xenc[b*2048+i];
        ds[i] = g_dsamp[d*2048+i];
    }
    __syncthreads();
    for (int i = tid; i < 4096; i += 256){
        int n = i >> 6, m = i & 63;
        float acc = 0.f;
        #pragma unroll
        for (int f = 0; f < 32; f++) acc += xs[n*32+f]*ds[m*32+f];
        Ms[n*65+m] = g_x2[b*64+n] + g_y2[d*64+m] - 2.f*acc;
    }
    __syncthreads();

    int paddr = (c & 15)*4 + (c >> 4);
    const float4* vw = g_vwd + d*4096;
    bool cInDn = (c < dn), cInNn = (c < nn);

    for (int l = 0; l < 8; l++){
        float lam = c_lamda[l];
        float regA[16], regB[16];
        #pragma unroll
        for (int n = 0; n < 16; n++){
            int row = q*16 + n;
            regA[n] = (row < nn && cInDn) ? __expf(-Ms[row*65 + c]*lam) : 0.f;
        }
        #pragma unroll
        for (int mm = 0; mm < 16; mm++){
            int col = q*16 + mm;
            regB[mm] = (cInNn && col < dn) ? __expf(-Ms[c*65 + col]*lam) : 0.f;
        }
        if (q == 0) ui_s[paddr] = 1.f;
        __syncthreads();

        float uic = 0.f;
        float vloc[16];
        for (int it = 0; it < 10; it++){
            // vi[c] = wjs_c / (sum_row Km[row][c]*ui[row] + eps)
            float p = 0.f;
            #pragma unroll
            for (int n = 0; n < 16; n++) p += regA[n] * ui_s[n*4 + q];
            p += __shfl_xor_sync(0xffffffffu, p, 1);
            p += __shfl_xor_sync(0xffffffffu, p, 2);
            if (q == 0) vi_s[paddr] = wjs_c / (p + 1e-6f);
            __syncthreads();
            // ui[c] = wis_c / (sum_col Km[c][col]*vi[col] + eps)
            p = 0.f;
            #pragma unroll
            for (int mm = 0; mm < 16; mm++){
                float v = vi_s[mm*4 + q];
                vloc[mm] = v;
                p += regB[mm] * v;
            }
            p += __shfl_xor_sync(0xffffffffu, p, 1);
            p += __shfl_xor_sync(0xffffffffu, p, 2);
            uic = wis_c / (p + 1e-6f);
            if (q == 0) ui_s[paddr] = uic;
            __syncthreads();
        }

        // row min/max of G[c][:] via shuffles (no smem)
        float gmx = -3.4e38f, gmn = 3.4e38f;
        #pragma unroll
        for (int mm = 0; mm < 16; mm++){
            float g = uic * regB[mm] * vloc[mm];
            gmx = fmaxf(gmx, g); gmn = fminf(gmn, g);
        }
        gmx = fmaxf(gmx, __shfl_xor_sync(0xffffffffu, gmx, 1));
        gmx = fmaxf(gmx, __shfl_xor_sync(0xffffffffu, gmx, 2));
        gmn = fminf(gmn, __shfl_xor_sync(0xffffffffu, gmn, 1));
        gmn = fminf(gmn, __shfl_xor_sync(0xffffffffu, gmn, 2));
        float rinv = 1.f / (gmx - gmn + 1e-6f);

        // fused projection epilogue
        float a0=0.f, a1=0.f, a2=0.f, a3=0.f;
        #pragma unroll
        for (int mm = 0; mm < 16; mm++){
            int col = q*16 + mm;
            float g  = uic * regB[mm] * vloc[mm];
            float gm = (g - gmn) * rinv * Ms[c*65 + col];
            float4 v = vw[c*64 + col];
            a0 += gm*v.x; a1 += gm*v.y; a2 += gm*v.z; a3 += gm*v.w;
        }
        #pragma unroll
        for (int o = 16; o; o >>= 1){
            a0 += __shfl_xor_sync(0xffffffffu, a0, o);
            a1 += __shfl_xor_sync(0xffffffffu, a1, o);
            a2 += __shfl_xor_sync(0xffffffffu, a2, o);
            a3 += __shfl_xor_sync(0xffffffffu, a3, o);
        }
        int wid = tid >> 5;
        if ((tid & 31) == 0) wred[wid] = make_float4(a0,a1,a2,a3);
        __syncthreads();
        if (tid == 0){
            float4 s = wred[0];
            #pragma unroll
            for (int w = 1; w < 8; w++){
                float4 t = wred[w];
                s.x += t.x; s.y += t.y; s.z += t.z; s.w += t.w;
            }
            g_part[(l*32+b)*30 + d] = s;
        }
    }
}

// ---------------- final: softmax over l + folded head + KL ----------------
__global__ void final_kernel(const float* __restrict__ fc1b,
    const float* __restrict__ fc2w, const float* __restrict__ fc2b,
    float* __restrict__ out, int out_size)
{
    __shared__ float4 pl[8];
    int b = blockIdx.x, tid = threadIdx.x;
    int w = tid >> 5, lane = tid & 31;

    float4 a = make_float4(0.f,0.f,0.f,0.f);
    if (lane < 30) a = g_part[(w*32+b)*30 + lane];
    #pragma unroll
    for (int o = 16; o; o >>= 1){
        a.x += __shfl_xor_sync(0xffffffffu, a.x, o);
        a.y += __shfl_xor_sync(0xffffffffu, a.y, o);
        a.z += __shfl_xor_sync(0xffffffffu, a.z, o);
        a.w += __shfl_xor_sync(0xffffffffu, a.w, o);
    }
    if (lane == 0) pl[w] = a;
    __syncthreads();
    if (tid == 0){
        float mx = pl[0].x;
        #pragma unroll
        for (int l = 1; l < 8; l++) mx = fmaxf(mx, pl[l].x);
        float s = 0.f;
        float co[8];
        #pragma unroll
        for (int l = 0; l < 8; l++){ co[l] = expf(pl[l].x - mx); s += co[l]; }
        float t0=0.f, t1=0.f, t2=0.f;
        #pragma unroll
        for (int l = 0; l < 8; l++){
            float cf = co[l]/s;
            t0 += cf*pl[l].y; t1 += cf*pl[l].z; t2 += cf*pl[l].w;
        }
        float cc0=fc2b[0], cc1=fc2b[1], cc2=fc2b[2];
        for (int r = 0; r < 64; r++){
            float fb = fc1b[r];
            cc0 += fc2w[r]*fb; cc1 += fc2w[64+r]*fb; cc2 += fc2w[128+r]*fb;
        }
        out[b*3+0] = t0 + cc0;
        out[b*3+1] = t1 + cc1;
        out[b*3+2] = t2 + cc2;
    }
    if (b == 0 && tid == 32 && out_size > 96){
        float s = 0.f;
        for (int d = 0; d < 30; d++) s += g_klpart[d];
        out[96] = s;
    }
}

// ---------------- launch ---------------------------------------------------
extern "C" void kernel_launch(void* const* d_in, const int* in_sizes, int n_in,
                              void* d_out, int out_size)
{
    const float* x          = (const float*)d_in[0];
    const float* adj        = (const float*)d_in[1];
    const int*   num_node   = (const int*)  d_in[2];
    const float* dict_feat  = (const float*)d_in[3];
    const float* dict_adj   = (const float*)d_in[4];
    const int*   dict_nnode = (const int*)  d_in[5];
    const float* eW1 = (const float*)d_in[6];
    const float* eb1 = (const float*)d_in[7];
    const float* eW2 = (const float*)d_in[8];
    const float* eb2 = (const float*)d_in[9];
    const float* eW3 = (const float*)d_in[10];
    const float* eb3 = (const float*)d_in[11];
    const float* dW1 = (const float*)d_in[12];
    const float* db1 = (const float*)d_in[13];
    const float* dW2 = (const float*)d_in[14];
    const float* db2 = (const float*)d_in[15];
    const float* dW3 = (const float*)d_in[16];
    const float* db3 = (const float*)d_in[17];
    const float* mlp_w  = (const float*)d_in[18];
    const float* mlp_b  = (const float*)d_in[19];
    const float* mlp2_w = (const float*)d_in[20];
    const float* mlp2_b = (const float*)d_in[21];
    const float* dist_para    = (const float*)d_in[22];
    const float* weight_lamda = (const float*)d_in[23];
    const float* fc1_w = (const float*)d_in[24];
    const float* fc1_b = (const float*)d_in[25];
    const float* fc2_w = (const float*)d_in[26];
    const float* fc2_b = (const float*)d_in[27];

    const int gcn_smem = (4096 + 4096 + 8192 + 8192) * (int)sizeof(float);  // 96 KB
    cudaFuncSetAttribute(gcn_kernel, cudaFuncAttributeMaxDynamicSharedMemorySize, gcn_smem);

    gcn_kernel<<<62, 256, gcn_smem>>>(x, adj, eW1, eb1, eW2, eb2, eW3, eb3,
                                      dict_feat, dict_adj, dW1, db1, dW2, db2, dW3, db3);
    prep_kernel<<<30, 256>>>(dist_para, weight_lamda, fc1_w, fc2_w,
                             mlp_w, mlp_b, mlp2_w, mlp2_b);
    sinkhorn_kernel<<<dim3(30, 32), 256>>>(num_node, dict_nnode);
    final_kernel<<<32, 256>>>(fc1_b, fc2_w, fc2_b, (float*)d_out, out_size);
}